// round 2
// baseline (speedup 1.0000x reference)
#include <cuda_runtime.h>
#include <cuda_bf16.h>

#define NPTS 1048576
#define KNEI 16

// Scratch: padded points (16B-aligned -> each random gather = exactly one
// 32B L2 sector), double accumulator, and a block-completion ticket counter.
__device__ float4 g_pts4[NPTS];
__device__ double g_acc;
__device__ unsigned int g_ticket;

// Kernel 1: pad [N,3] f32 -> [N] float4 (vectorized: 4 points per thread)
// and reset accumulator + ticket (must happen every graph replay).
__global__ void __launch_bounds__(256) pad_points_kernel(const float* __restrict__ pts) {
    int i = blockIdx.x * blockDim.x + threadIdx.x;   // 0 .. 262143
    if (i == 0) { g_acc = 0.0; g_ticket = 0u; }

    const float4* p4 = reinterpret_cast<const float4*>(pts) + 3 * i;
    float4 a = p4[0];
    float4 b = p4[1];
    float4 c = p4[2];

    int o = 4 * i;
    g_pts4[o + 0] = make_float4(a.x, a.y, a.z, 0.0f);
    g_pts4[o + 1] = make_float4(a.w, b.x, b.y, 0.0f);
    g_pts4[o + 2] = make_float4(b.z, b.w, c.x, 0.0f);
    g_pts4[o + 3] = make_float4(c.y, c.z, c.w, 0.0f);
}

// Kernel 2: one thread per source point; gathers done in 2 batches of 8 to
// keep register pressure <=64 (4 CTAs/SM). Grid exactly covers NPTS.
__global__ void __launch_bounds__(256, 4) neighbour_loss_kernel(
    const int* __restrict__ idx,
    const float* __restrict__ orig,
    float* __restrict__ out)
{
    int n = blockIdx.x * blockDim.x + threadIdx.x;

    float4 p = g_pts4[n];
    const int4*   idx4  = reinterpret_cast<const int4*>(idx)   + n * 4;
    const float4* orig4 = reinterpret_cast<const float4*>(orig) + n * 4;

    float tsum = 0.0f;

    #pragma unroll
    for (int b = 0; b < 2; ++b) {
        int4   i0 = idx4[2 * b + 0];
        int4   i1 = idx4[2 * b + 1];
        float4 o0 = orig4[2 * b + 0];
        float4 o1 = orig4[2 * b + 1];

        // 8 independent 16B gathers -> 8 outstanding sectors per thread.
        float4 q0 = __ldg(&g_pts4[i0.x]);
        float4 q1 = __ldg(&g_pts4[i0.y]);
        float4 q2 = __ldg(&g_pts4[i0.z]);
        float4 q3 = __ldg(&g_pts4[i0.w]);
        float4 q4 = __ldg(&g_pts4[i1.x]);
        float4 q5 = __ldg(&g_pts4[i1.y]);
        float4 q6 = __ldg(&g_pts4[i1.z]);
        float4 q7 = __ldg(&g_pts4[i1.w]);

        float dx, dy, dz, curr, e;
        #define ACC(q, ov)                                        \
            dx = p.x - q.x; dy = p.y - q.y; dz = p.z - q.z;       \
            curr = fmaf(dx, dx, fmaf(dy, dy, dz * dz));           \
            e = curr - ov;                                        \
            tsum = fmaf(e, e, tsum);
        ACC(q0, o0.x) ACC(q1, o0.y) ACC(q2, o0.z) ACC(q3, o0.w)
        ACC(q4, o1.x) ACC(q5, o1.y) ACC(q6, o1.z) ACC(q7, o1.w)
        #undef ACC
    }

    // Warp reduce
    #pragma unroll
    for (int off = 16; off > 0; off >>= 1)
        tsum += __shfl_down_sync(0xFFFFFFFFu, tsum, off);

    // Block reduce via shared
    __shared__ float warp_sums[8];
    int lane = threadIdx.x & 31;
    int wid  = threadIdx.x >> 5;
    if (lane == 0) warp_sums[wid] = tsum;
    __syncthreads();
    if (wid == 0) {
        float bs = (lane < 8) ? warp_sums[lane] : 0.0f;
        #pragma unroll
        for (int off = 4; off > 0; off >>= 1)
            bs += __shfl_down_sync(0xFFFFFFFFu, bs, off);
        if (lane == 0) {
            atomicAdd(&g_acc, (double)bs);
            __threadfence();
            unsigned t = atomicAdd(&g_ticket, 1u);
            if (t == gridDim.x - 1) {
                // Last block: all prior g_acc adds are visible (fence+atomic).
                double total = atomicAdd(&g_acc, 0.0);   // atomic read
                out[0] = (float)(total * (100000.0 / 16777216.0));
            }
        }
    }
}

extern "C" void kernel_launch(void* const* d_in, const int* in_sizes, int n_in,
                              void* d_out, int out_size) {
    const float* points = (const float*)d_in[0];
    const int*   nidx   = (const int*)d_in[1];
    const float* orig   = (const float*)d_in[2];
    float* out = (float*)d_out;

    (void)in_sizes; (void)n_in; (void)out_size;

    pad_points_kernel<<<1024, 256>>>(points);                  // 4 pts/thread
    neighbour_loss_kernel<<<4096, 256>>>(nidx, orig, out);     // 1 pt/thread
}

// round 3
// speedup vs baseline: 1.1045x; 1.1045x over previous
#include <cuda_runtime.h>
#include <cuda_bf16.h>

#define NPTS 1048576
#define KNEI 16

// Padded points: 16B-aligned -> each random gather = exactly one 32B L2
// sector / one L1tex wavefront per lane.
__device__ float4 g_pts4[NPTS];
__device__ double g_acc;
__device__ unsigned int g_ticket;

// Kernel 1: pad [N,3] f32 -> [N] float4 (4 points per thread) and reset
// accumulator + ticket (must happen on every graph replay).
__global__ void __launch_bounds__(256) pad_points_kernel(const float* __restrict__ pts) {
    int i = blockIdx.x * blockDim.x + threadIdx.x;   // 0 .. 262143
    if (i == 0) { g_acc = 0.0; g_ticket = 0u; }

    const float4* p4 = reinterpret_cast<const float4*>(pts) + 3 * i;
    float4 a = p4[0];
    float4 b = p4[1];
    float4 c = p4[2];

    int o = 4 * i;
    g_pts4[o + 0] = make_float4(a.x, a.y, a.z, 0.0f);
    g_pts4[o + 1] = make_float4(a.w, b.x, b.y, 0.0f);
    g_pts4[o + 2] = make_float4(b.z, b.w, c.x, 0.0f);
    g_pts4[o + 3] = make_float4(c.y, c.z, c.w, 0.0f);
}

// Kernel 2: 2 threads per point, 8 neighbours each. All 8 gathers are
// independent and issued together (no batch serialization); ~44 regs ->
// high occupancy AND high per-thread MLP.
__global__ void __launch_bounds__(256) neighbour_loss_kernel(
    const int* __restrict__ idx,
    const float* __restrict__ orig,
    float* __restrict__ out)
{
    int t = blockIdx.x * blockDim.x + threadIdx.x;   // 0 .. 2*NPTS-1
    int n = t >> 1;                                   // point id

    // This thread's 8 indices (2 x int4, fully coalesced).
    const int4* idx4 = reinterpret_cast<const int4*>(idx) + t * 2;
    int4 i0 = idx4[0];
    int4 i1 = idx4[1];

    // 8 independent 16B gathers — all in flight simultaneously.
    float4 q0 = __ldg(&g_pts4[i0.x]);
    float4 q1 = __ldg(&g_pts4[i0.y]);
    float4 q2 = __ldg(&g_pts4[i0.z]);
    float4 q3 = __ldg(&g_pts4[i0.w]);
    float4 q4 = __ldg(&g_pts4[i1.x]);
    float4 q5 = __ldg(&g_pts4[i1.y]);
    float4 q6 = __ldg(&g_pts4[i1.z]);
    float4 q7 = __ldg(&g_pts4[i1.w]);

    // Streamed loads overlap the gathers.
    const float4* orig4 = reinterpret_cast<const float4*>(orig) + t * 2;
    float4 o0 = orig4[0];
    float4 o1 = orig4[1];
    float4 p  = g_pts4[n];   // broadcast pair-shared, L1-friendly

    float tsum = 0.0f;
    float dx, dy, dz, curr, e;
    #define ACC(q, ov)                                        \
        dx = p.x - q.x; dy = p.y - q.y; dz = p.z - q.z;       \
        curr = fmaf(dx, dx, fmaf(dy, dy, dz * dz));           \
        e = curr - ov;                                        \
        tsum = fmaf(e, e, tsum);
    ACC(q0, o0.x) ACC(q1, o0.y) ACC(q2, o0.z) ACC(q3, o0.w)
    ACC(q4, o1.x) ACC(q5, o1.y) ACC(q6, o1.z) ACC(q7, o1.w)
    #undef ACC

    // Warp reduce
    #pragma unroll
    for (int off = 16; off > 0; off >>= 1)
        tsum += __shfl_down_sync(0xFFFFFFFFu, tsum, off);

    // Block reduce via shared
    __shared__ float warp_sums[8];
    int lane = threadIdx.x & 31;
    int wid  = threadIdx.x >> 5;
    if (lane == 0) warp_sums[wid] = tsum;
    __syncthreads();
    if (wid == 0) {
        float bs = (lane < 8) ? warp_sums[lane] : 0.0f;
        #pragma unroll
        for (int off = 4; off > 0; off >>= 1)
            bs += __shfl_down_sync(0xFFFFFFFFu, bs, off);
        if (lane == 0) {
            atomicAdd(&g_acc, (double)bs);
            __threadfence();
            unsigned tk = atomicAdd(&g_ticket, 1u);
            if (tk == gridDim.x - 1) {
                double total = atomicAdd(&g_acc, 0.0);   // atomic read
                out[0] = (float)(total * (100000.0 / 16777216.0));
            }
        }
    }
}

extern "C" void kernel_launch(void* const* d_in, const int* in_sizes, int n_in,
                              void* d_out, int out_size) {
    const float* points = (const float*)d_in[0];
    const int*   nidx   = (const int*)d_in[1];
    const float* orig   = (const float*)d_in[2];
    float* out = (float*)d_out;

    (void)in_sizes; (void)n_in; (void)out_size;

    pad_points_kernel<<<1024, 256>>>(points);                   // 4 pts/thread
    neighbour_loss_kernel<<<8192, 256>>>(nidx, orig, out);      // 8 nbrs/thread
}

// round 4
// speedup vs baseline: 1.1203x; 1.0142x over previous
#include <cuda_runtime.h>
#include <cuda_bf16.h>

#define NPTS 1048576
#define KNEI 16
#define NTASKS (2 * NPTS)          // 2 threads (tasks) per point, 8 nbrs each
#define GRID_MAIN 888              // 148 SMs x 6 blocks (40 regs, 256 thr)

// Padded points: 16B-aligned -> each random gather = exactly one 32B L2
// sector / one L1tex wavefront per lane.
__device__ float4 g_pts4[NPTS];
__device__ double g_acc;
__device__ unsigned int g_ticket;

// Kernel 1: pad [N,3] f32 -> [N] float4 (4 points per thread) and reset
// accumulator + ticket (must happen on every graph replay).
__global__ void __launch_bounds__(256) pad_points_kernel(const float* __restrict__ pts) {
    int i = blockIdx.x * blockDim.x + threadIdx.x;   // 0 .. 262143
    if (i == 0) { g_acc = 0.0; g_ticket = 0u; }

    const float4* p4 = reinterpret_cast<const float4*>(pts) + 3 * i;
    float4 a = p4[0];
    float4 b = p4[1];
    float4 c = p4[2];

    int o = 4 * i;
    g_pts4[o + 0] = make_float4(a.x, a.y, a.z, 0.0f);
    g_pts4[o + 1] = make_float4(a.w, b.x, b.y, 0.0f);
    g_pts4[o + 2] = make_float4(b.z, b.w, c.x, 0.0f);
    g_pts4[o + 3] = make_float4(c.y, c.z, c.w, 0.0f);
}

// Kernel 2: persistent grid; each thread handles ~9 pair-tasks (8 neighbours
// each) via grid-stride loop. All 8 gathers per task are independent and in
// flight together; consecutive iterations overlap in the memory pipeline.
__global__ void __launch_bounds__(256, 6) neighbour_loss_kernel(
    const int* __restrict__ idx,
    const float* __restrict__ orig,
    float* __restrict__ out)
{
    const int stride = GRID_MAIN * 256;
    float tsum = 0.0f;

    for (int t = blockIdx.x * 256 + threadIdx.x; t < NTASKS; t += stride) {
        int n = t >> 1;   // point id

        // This task's 8 indices (2 x int4, fully coalesced).
        const int4* idx4 = reinterpret_cast<const int4*>(idx) + t * 2;
        int4 i0 = idx4[0];
        int4 i1 = idx4[1];

        // 8 independent 16B gathers — all outstanding simultaneously.
        float4 q0 = __ldg(&g_pts4[i0.x]);
        float4 q1 = __ldg(&g_pts4[i0.y]);
        float4 q2 = __ldg(&g_pts4[i0.z]);
        float4 q3 = __ldg(&g_pts4[i0.w]);
        float4 q4 = __ldg(&g_pts4[i1.x]);
        float4 q5 = __ldg(&g_pts4[i1.y]);
        float4 q6 = __ldg(&g_pts4[i1.z]);
        float4 q7 = __ldg(&g_pts4[i1.w]);

        // Streamed loads overlap the gathers.
        const float4* orig4 = reinterpret_cast<const float4*>(orig) + t * 2;
        float4 o0 = orig4[0];
        float4 o1 = orig4[1];
        float4 p  = g_pts4[n];

        float dx, dy, dz, curr, e;
        #define ACC(q, ov)                                        \
            dx = p.x - q.x; dy = p.y - q.y; dz = p.z - q.z;       \
            curr = fmaf(dx, dx, fmaf(dy, dy, dz * dz));           \
            e = curr - ov;                                        \
            tsum = fmaf(e, e, tsum);
        ACC(q0, o0.x) ACC(q1, o0.y) ACC(q2, o0.z) ACC(q3, o0.w)
        ACC(q4, o1.x) ACC(q5, o1.y) ACC(q6, o1.z) ACC(q7, o1.w)
        #undef ACC
    }

    // Warp reduce (once per thread, after all iterations)
    #pragma unroll
    for (int off = 16; off > 0; off >>= 1)
        tsum += __shfl_down_sync(0xFFFFFFFFu, tsum, off);

    // Block reduce via shared
    __shared__ float warp_sums[8];
    int lane = threadIdx.x & 31;
    int wid  = threadIdx.x >> 5;
    if (lane == 0) warp_sums[wid] = tsum;
    __syncthreads();
    if (wid == 0) {
        float bs = (lane < 8) ? warp_sums[lane] : 0.0f;
        #pragma unroll
        for (int off = 4; off > 0; off >>= 1)
            bs += __shfl_down_sync(0xFFFFFFFFu, bs, off);
        if (lane == 0) {
            atomicAdd(&g_acc, (double)bs);
            __threadfence();
            unsigned tk = atomicAdd(&g_ticket, 1u);
            if (tk == GRID_MAIN - 1) {
                double total = atomicAdd(&g_acc, 0.0);   // atomic read
                out[0] = (float)(total * (100000.0 / 16777216.0));
            }
        }
    }
}

extern "C" void kernel_launch(void* const* d_in, const int* in_sizes, int n_in,
                              void* d_out, int out_size) {
    const float* points = (const float*)d_in[0];
    const int*   nidx   = (const int*)d_in[1];
    const float* orig   = (const float*)d_in[2];
    float* out = (float*)d_out;

    (void)in_sizes; (void)n_in; (void)out_size;

    pad_points_kernel<<<1024, 256>>>(points);                    // 4 pts/thread
    neighbour_loss_kernel<<<GRID_MAIN, 256>>>(nidx, orig, out);  // persistent
}